// round 3
// baseline (speedup 1.0000x reference)
#include <cuda_runtime.h>

#define NN 50000
#define NE 800000
#define DD 256

// Scratch (no allocations allowed): ~109 MB static device memory.
__device__ float g_x[NN * DD];    // current activations
__device__ float g_h[NN * DD];    // post-GEMM, pre-aggregation
__device__ float g_deg[NN];
__device__ float g_dinv[NN];
__device__ int   g_src[NE];
__device__ int   g_dst[NE];
__device__ int   g_odd_nonzero;   // dtype sniffer flag

// ---------------------------------------------------------------------------
// edge_index dtype detection + decode (int32 vs int64 robustness)
// ---------------------------------------------------------------------------
__global__ void flags_init_kernel() {
    if (threadIdx.x == 0 && blockIdx.x == 0) g_odd_nonzero = 0;
}

// Sample first 8192 int32 words; int64 data => all odd words are zero.
__global__ void detect_kernel(const int* __restrict__ ei32) {
    int i = blockIdx.x * blockDim.x + threadIdx.x;   // 0..8191
    if ((i & 1) && ei32[i] != 0) atomicOr(&g_odd_nonzero, 1);
}

__global__ void decode_kernel(const int* __restrict__ ei32) {
    int e = blockIdx.x * blockDim.x + threadIdx.x;
    if (e >= NE) return;
    if (g_odd_nonzero) {            // genuinely int32: [src[NE] | dst[NE]]
        g_src[e] = ei32[e];
        g_dst[e] = ei32[NE + e];
    } else {                        // int64: low words at even offsets
        g_src[e] = ei32[2 * e];
        g_dst[e] = ei32[2 * (NE + e)];
    }
}

// ---------------------------------------------------------------------------
// Degree / normalization
// ---------------------------------------------------------------------------
__global__ void deg_init_kernel() {
    int i = blockIdx.x * blockDim.x + threadIdx.x;
    if (i < NN) g_deg[i] = 1.0f;   // self loop
}

__global__ void deg_count_kernel() {
    int e = blockIdx.x * blockDim.x + threadIdx.x;
    if (e < NE) atomicAdd(&g_deg[g_dst[e]], 1.0f);
}

__global__ void dinv_kernel() {
    int i = blockIdx.x * blockDim.x + threadIdx.x;
    if (i < NN) g_dinv[i] = rsqrtf(g_deg[i]);
}

// ---------------------------------------------------------------------------
// SGEMM: C[M,256] = A[M,256] @ B[256,256] (+bias, +relu optional)
// 64x64 tile, 256 threads, 4x4 microtile, BK=16.
// a_sel: 0 -> A = Ain (external), 1 -> A = g_x
// c_sel: 0 -> C = g_x,            1 -> C = g_h
// ---------------------------------------------------------------------------
__global__ void __launch_bounds__(256)
gemm_kernel(const float* __restrict__ Ain, const float* __restrict__ B,
            const float* __restrict__ bias, int a_sel, int c_sel, int relu)
{
    const float* A = (a_sel == 0) ? Ain : g_x;
    float*       C = (c_sel == 0) ? g_x : g_h;

    __shared__ float As[16][64];
    __shared__ float Bs[16][64];
    const int tid  = threadIdx.x;
    const int row0 = blockIdx.x * 64;
    const int col0 = blockIdx.y * 64;
    const int ty = tid >> 4;      // 0..15
    const int tx = tid & 15;      // 0..15

    float acc[4][4] = {};

    for (int k0 = 0; k0 < DD; k0 += 16) {
#pragma unroll
        for (int it = 0; it < 4; it++) {
            int i = tid + it * 256;          // 0..1023
            int m = i >> 4, k = i & 15;
            int r = row0 + m;
            As[k][m] = (r < NN) ? A[(size_t)r * DD + k0 + k] : 0.0f;
        }
#pragma unroll
        for (int it = 0; it < 4; it++) {
            int i = tid + it * 256;
            int k = i >> 6, n = i & 63;
            Bs[k][n] = B[(size_t)(k0 + k) * DD + col0 + n];
        }
        __syncthreads();
#pragma unroll
        for (int k = 0; k < 16; k++) {
            float4 a = *(const float4*)&As[k][ty << 2];
            float4 b = *(const float4*)&Bs[k][tx << 2];
            acc[0][0] += a.x * b.x; acc[0][1] += a.x * b.y; acc[0][2] += a.x * b.z; acc[0][3] += a.x * b.w;
            acc[1][0] += a.y * b.x; acc[1][1] += a.y * b.y; acc[1][2] += a.y * b.z; acc[1][3] += a.y * b.w;
            acc[2][0] += a.z * b.x; acc[2][1] += a.z * b.y; acc[2][2] += a.z * b.z; acc[2][3] += a.z * b.w;
            acc[3][0] += a.w * b.x; acc[3][1] += a.w * b.y; acc[3][2] += a.w * b.z; acc[3][3] += a.w * b.w;
        }
        __syncthreads();
    }

    const int c = col0 + (tx << 2);
#pragma unroll
    for (int i = 0; i < 4; i++) {
        int r = row0 + (ty << 2) + i;
        if (r < NN) {
            float4 v;
            v.x = acc[i][0]; v.y = acc[i][1]; v.z = acc[i][2]; v.w = acc[i][3];
            if (bias) {
                float4 bb = *(const float4*)&bias[c];
                v.x += bb.x; v.y += bb.y; v.z += bb.z; v.w += bb.w;
            }
            if (relu) {
                v.x = fmaxf(v.x, 0.f); v.y = fmaxf(v.y, 0.f);
                v.z = fmaxf(v.z, 0.f); v.w = fmaxf(v.w, 0.f);
            }
            *(float4*)&C[(size_t)r * DD + c] = v;
        }
    }
}

// ---------------------------------------------------------------------------
// Accumulator init with self-loop term: y[i] = dinv[i]^2 * g_h[i]
// ---------------------------------------------------------------------------
__global__ void selfloop_kernel(float* __restrict__ y)
{
    int idx = blockIdx.x * blockDim.x + threadIdx.x;   // float4 index
    if (idx < NN * DD / 4) {
        int node = idx >> 6;                            // DD/4 = 64 float4 per row
        float s = g_dinv[node];
        s = s * s;
        float4 v = ((const float4*)g_h)[idx];
        v.x *= s; v.y *= s; v.z *= s; v.w *= s;
        ((float4*)y)[idx] = v;
    }
}

// ---------------------------------------------------------------------------
// Edge scatter: one warp per edge; lane handles 2 float4 chunks (8 floats).
// Vector L2 reductions (red.global.add.v4.f32, sm_90+): 64 atomics/edge.
// ---------------------------------------------------------------------------
__global__ void scatter_kernel(float* __restrict__ y)
{
    int gid  = blockIdx.x * blockDim.x + threadIdx.x;
    int e    = gid >> 5;
    int lane = gid & 31;
    if (e >= NE) return;
    int s = g_src[e];
    int d = g_dst[e];
    float norm = g_dinv[s] * g_dinv[d];
    const float4* hr = (const float4*)(g_h + (size_t)s * DD);
    float4*       yr = (float4*)(y + (size_t)d * DD);
#pragma unroll
    for (int c = 0; c < 2; c++) {
        float4 v = hr[lane + 32 * c];
        v.x *= norm; v.y *= norm; v.z *= norm; v.w *= norm;
        asm volatile("red.global.add.v4.f32 [%0], {%1,%2,%3,%4};"
                     :: "l"(yr + lane + 32 * c),
                        "f"(v.x), "f"(v.y), "f"(v.z), "f"(v.w)
                     : "memory");
    }
}

// ---------------------------------------------------------------------------
// Epilogue: o = relu(y + bias_row).  o_sel: 0 -> g_x, 1 -> Oin (external)
// ---------------------------------------------------------------------------
__global__ void epilogue_kernel(const float* __restrict__ y,
                                const float* __restrict__ b,
                                float* __restrict__ Oin, int o_sel)
{
    float* o = (o_sel == 0) ? g_x : Oin;
    int idx = blockIdx.x * blockDim.x + threadIdx.x;   // float4 index
    if (idx < NN * DD / 4) {
        float4 v  = ((const float4*)y)[idx];
        float4 bb = ((const float4*)b)[idx & 63];
        v.x = fmaxf(v.x + bb.x, 0.f);
        v.y = fmaxf(v.y + bb.y, 0.f);
        v.z = fmaxf(v.z + bb.z, 0.f);
        v.w = fmaxf(v.w + bb.w, 0.f);
        ((float4*)o)[idx] = v;
    }
}

// ---------------------------------------------------------------------------
// Launch — kernels only; no runtime API calls (graph-capture safe).
// ---------------------------------------------------------------------------
extern "C" void kernel_launch(void* const* d_in, const int* in_sizes, int n_in,
                              void* d_out, int out_size)
{
    const float* input  = (const float*)d_in[0];
    const int*   ei32   = (const int*)d_in[1];     // int32 view; dtype sniffed on device
    const float* weight = (const float*)d_in[2];
    const float* bias   = (const float*)d_in[3];
    const float* conv_w = (const float*)d_in[4];
    const float* conv_b = (const float*)d_in[5];
    float*       out    = (float*)d_out;

    // Decode edge_index robustly (int32 or int64 on disk).
    flags_init_kernel<<<1, 32>>>();
    detect_kernel<<<8192 / 256, 256>>>(ei32);
    decode_kernel<<<(NE + 255) / 256, 256>>>(ei32);

    // Degree + dinv
    deg_init_kernel<<<(NN + 255) / 256, 256>>>();
    deg_count_kernel<<<(NE + 255) / 256, 256>>>();
    dinv_kernel<<<(NN + 255) / 256, 256>>>();

    dim3 ggrid((NN + 63) / 64, DD / 64);

    // x = relu(input @ W + b)   (A = input, C = g_x)
    gemm_kernel<<<ggrid, 256>>>(input, weight, bias, /*a_sel=*/0, /*c_sel=*/0, /*relu=*/1);

    const int nd4_blocks = (NN * DD / 4) / 256;   // 12500, exact
    for (int l = 0; l < 2; l++) {
        // h = x @ conv_w[l]   (A = g_x, C = g_h)
        gemm_kernel<<<ggrid, 256>>>(nullptr, conv_w + (size_t)l * DD * DD,
                                    nullptr, /*a_sel=*/1, /*c_sel=*/1, /*relu=*/0);
        // y = dinv^2 * h  (self-loop, also initializes the accumulator in d_out)
        selfloop_kernel<<<nd4_blocks, 256>>>(out);
        // y[d] += dinv[s]*dinv[d] * h[s] over edges
        scatter_kernel<<<(NE * 32) / 256, 256>>>(out);
        // layer0 -> g_x, layer1 -> d_out (in place)
        epilogue_kernel<<<nd4_blocks, 256>>>(out, conv_b + l * DD,
                                             out, /*o_sel=*/(l == 0) ? 0 : 1);
    }
}

// round 4
// speedup vs baseline: 1.1349x; 1.1349x over previous
#include <cuda_runtime.h>

#define NN 50000
#define NE 800000
#define DD 256

// Static scratch (no allocations allowed): ~113 MB.
__device__ float g_x[NN * DD];      // current activations
__device__ float g_h[NN * DD];      // post-GEMM, pre-aggregation
__device__ float g_dinv[NN];
__device__ int   g_src[NE];
__device__ int   g_dst[NE];
__device__ int   g_esrc[NE];        // CSR: src ids grouped by dst
__device__ int   g_cnt[NN];         // in-degree (edges only)
__device__ int   g_rowstart[NN + 1];
__device__ int   g_fill[NN];
__device__ int   g_odd_nonzero;     // dtype sniffer flag

// ---------------------------------------------------------------------------
// Setup: dtype sniff, decode+histogram, scan(+dinv), CSR fill
// ---------------------------------------------------------------------------
__global__ void init_kernel() {          // zero cnt + flag
    int i = blockIdx.x * blockDim.x + threadIdx.x;
    if (i < NN) g_cnt[i] = 0;
    if (i == 0) g_odd_nonzero = 0;
}

// Sample first 8192 int32 words; int64 data => all odd words are zero.
__global__ void detect_kernel(const int* __restrict__ ei32) {
    int i = blockIdx.x * blockDim.x + threadIdx.x;   // 0..8191
    if ((i & 1) && ei32[i] != 0) atomicOr(&g_odd_nonzero, 1);
}

__global__ void decode_hist_kernel(const int* __restrict__ ei32) {
    int e = blockIdx.x * blockDim.x + threadIdx.x;
    if (e >= NE) return;
    int s, d;
    if (g_odd_nonzero) {            // genuinely int32: [src[NE] | dst[NE]]
        s = ei32[e];
        d = ei32[NE + e];
    } else {                        // int64: low words at even offsets
        s = ei32[2 * e];
        d = ei32[2 * (NE + e)];
    }
    g_src[e] = s;
    g_dst[e] = d;
    atomicAdd(&g_cnt[d], 1);
}

// Single-block exclusive scan over g_cnt; also writes dinv and zeroes fill.
__global__ void __launch_bounds__(1024) scan_kernel() {
    __shared__ int ssum[1024];
    const int CH = (NN + 1023) / 1024;   // 49
    int t = threadIdx.x;
    int base = t * CH;
    int local = 0;
    for (int j = 0; j < CH; j++) {
        int i = base + j;
        if (i < NN) local += g_cnt[i];
    }
    ssum[t] = local;
    __syncthreads();
    for (int off = 1; off < 1024; off <<= 1) {
        int v = ssum[t];
        int add = (t >= off) ? ssum[t - off] : 0;
        __syncthreads();
        ssum[t] = v + add;
        __syncthreads();
    }
    int run = ssum[t] - local;           // exclusive prefix
    for (int j = 0; j < CH; j++) {
        int i = base + j;
        if (i < NN) {
            int c = g_cnt[i];
            g_rowstart[i] = run;
            run += c;
            g_fill[i] = 0;
            g_dinv[i] = rsqrtf((float)c + 1.0f);   // +1 self loop
        }
    }
    if (t == 1023) g_rowstart[NN] = NE;
}

__global__ void fill_kernel() {
    int e = blockIdx.x * blockDim.x + threadIdx.x;
    if (e >= NE) return;
    int d = g_dst[e];
    int pos = g_rowstart[d] + atomicAdd(&g_fill[d], 1);
    g_esrc[pos] = g_src[e];
}

// ---------------------------------------------------------------------------
// SGEMM: C[M,256] = A[M,256] @ B[256,256] (+bias, +relu optional)
// 64x64 tile, 256 threads, 4x4 microtile, BK=16.
// a_sel: 0 -> A = Ain (external), 1 -> A = g_x ; C = g_x (c_sel=0) / g_h (1)
// ---------------------------------------------------------------------------
__global__ void __launch_bounds__(256)
gemm_kernel(const float* __restrict__ Ain, const float* __restrict__ B,
            const float* __restrict__ bias, int a_sel, int c_sel, int relu)
{
    const float* A = (a_sel == 0) ? Ain : g_x;
    float*       C = (c_sel == 0) ? g_x : g_h;

    __shared__ float As[16][64];
    __shared__ float Bs[16][64];
    const int tid  = threadIdx.x;
    const int row0 = blockIdx.x * 64;
    const int col0 = blockIdx.y * 64;
    const int ty = tid >> 4;      // 0..15
    const int tx = tid & 15;      // 0..15

    float acc[4][4] = {};

    for (int k0 = 0; k0 < DD; k0 += 16) {
#pragma unroll
        for (int it = 0; it < 4; it++) {
            int i = tid + it * 256;          // 0..1023
            int m = i >> 4, k = i & 15;
            int r = row0 + m;
            As[k][m] = (r < NN) ? A[(size_t)r * DD + k0 + k] : 0.0f;
        }
#pragma unroll
        for (int it = 0; it < 4; it++) {
            int i = tid + it * 256;
            int k = i >> 6, n = i & 63;
            Bs[k][n] = B[(size_t)(k0 + k) * DD + col0 + n];
        }
        __syncthreads();
#pragma unroll
        for (int k = 0; k < 16; k++) {
            float4 a = *(const float4*)&As[k][ty << 2];
            float4 b = *(const float4*)&Bs[k][tx << 2];
            acc[0][0] += a.x * b.x; acc[0][1] += a.x * b.y; acc[0][2] += a.x * b.z; acc[0][3] += a.x * b.w;
            acc[1][0] += a.y * b.x; acc[1][1] += a.y * b.y; acc[1][2] += a.y * b.z; acc[1][3] += a.y * b.w;
            acc[2][0] += a.z * b.x; acc[2][1] += a.z * b.y; acc[2][2] += a.z * b.z; acc[2][3] += a.z * b.w;
            acc[3][0] += a.w * b.x; acc[3][1] += a.w * b.y; acc[3][2] += a.w * b.z; acc[3][3] += a.w * b.w;
        }
        __syncthreads();
    }

    const int c = col0 + (tx << 2);
#pragma unroll
    for (int i = 0; i < 4; i++) {
        int r = row0 + (ty << 2) + i;
        if (r < NN) {
            float4 v;
            v.x = acc[i][0]; v.y = acc[i][1]; v.z = acc[i][2]; v.w = acc[i][3];
            if (bias) {
                float4 bb = *(const float4*)&bias[c];
                v.x += bb.x; v.y += bb.y; v.z += bb.z; v.w += bb.w;
            }
            if (relu) {
                v.x = fmaxf(v.x, 0.f); v.y = fmaxf(v.y, 0.f);
                v.z = fmaxf(v.z, 0.f); v.w = fmaxf(v.w, 0.f);
            }
            *(float4*)&C[(size_t)r * DD + c] = v;
        }
    }
}

// ---------------------------------------------------------------------------
// Fused CSR aggregation: one warp per dst node.
//   o[d] = relu( bias + dinv[d]^2 * h[d] + sum_{s in N(d)} dinv[s]dinv[d] h[s] )
// Lane holds float4 columns {lane, lane+32} (8 floats) in registers.
// ---------------------------------------------------------------------------
__global__ void __launch_bounds__(256)
aggregate_kernel(const float* __restrict__ bias, float* __restrict__ Oin, int o_sel)
{
    float* o = (o_sel == 0) ? g_x : Oin;
    int warp = (blockIdx.x * blockDim.x + threadIdx.x) >> 5;
    int lane = threadIdx.x & 31;
    if (warp >= NN) return;
    const int d = warp;
    const float dv = g_dinv[d];

    // self-loop init
    const float4* hd = (const float4*)(g_h + (size_t)d * DD);
    float4 a0 = hd[lane];
    float4 a1 = hd[lane + 32];
    const float s2 = dv * dv;
    a0.x *= s2; a0.y *= s2; a0.z *= s2; a0.w *= s2;
    a1.x *= s2; a1.y *= s2; a1.z *= s2; a1.w *= s2;

    const int start = g_rowstart[d];
    const int end   = g_rowstart[d + 1];
    int i = start;
    for (; i + 2 <= end; i += 2) {
        int s0 = g_esrc[i];
        int s1 = g_esrc[i + 1];
        float n0 = dv * g_dinv[s0];
        float n1 = dv * g_dinv[s1];
        const float4* h0 = (const float4*)(g_h + (size_t)s0 * DD);
        const float4* h1 = (const float4*)(g_h + (size_t)s1 * DD);
        float4 v00 = h0[lane], v01 = h0[lane + 32];
        float4 v10 = h1[lane], v11 = h1[lane + 32];
        a0.x += n0 * v00.x; a0.y += n0 * v00.y; a0.z += n0 * v00.z; a0.w += n0 * v00.w;
        a1.x += n0 * v01.x; a1.y += n0 * v01.y; a1.z += n0 * v01.z; a1.w += n0 * v01.w;
        a0.x += n1 * v10.x; a0.y += n1 * v10.y; a0.z += n1 * v10.z; a0.w += n1 * v10.w;
        a1.x += n1 * v11.x; a1.y += n1 * v11.y; a1.z += n1 * v11.z; a1.w += n1 * v11.w;
    }
    if (i < end) {
        int s0 = g_esrc[i];
        float n0 = dv * g_dinv[s0];
        const float4* h0 = (const float4*)(g_h + (size_t)s0 * DD);
        float4 v00 = h0[lane], v01 = h0[lane + 32];
        a0.x += n0 * v00.x; a0.y += n0 * v00.y; a0.z += n0 * v00.z; a0.w += n0 * v00.w;
        a1.x += n0 * v01.x; a1.y += n0 * v01.y; a1.z += n0 * v01.z; a1.w += n0 * v01.w;
    }

    // bias + relu + store
    float4 b0 = ((const float4*)bias)[lane];
    float4 b1 = ((const float4*)bias)[lane + 32];
    a0.x = fmaxf(a0.x + b0.x, 0.f); a0.y = fmaxf(a0.y + b0.y, 0.f);
    a0.z = fmaxf(a0.z + b0.z, 0.f); a0.w = fmaxf(a0.w + b0.w, 0.f);
    a1.x = fmaxf(a1.x + b1.x, 0.f); a1.y = fmaxf(a1.y + b1.y, 0.f);
    a1.z = fmaxf(a1.z + b1.z, 0.f); a1.w = fmaxf(a1.w + b1.w, 0.f);
    float4* orow = (float4*)(o + (size_t)d * DD);
    orow[lane] = a0;
    orow[lane + 32] = a1;
}

// ---------------------------------------------------------------------------
// Launch — kernels only; no runtime API calls (graph-capture safe).
// ---------------------------------------------------------------------------
extern "C" void kernel_launch(void* const* d_in, const int* in_sizes, int n_in,
                              void* d_out, int out_size)
{
    const float* input  = (const float*)d_in[0];
    const int*   ei32   = (const int*)d_in[1];     // int32 view; dtype sniffed on device
    const float* weight = (const float*)d_in[2];
    const float* bias   = (const float*)d_in[3];
    const float* conv_w = (const float*)d_in[4];
    const float* conv_b = (const float*)d_in[5];
    float*       out    = (float*)d_out;

    // CSR build
    init_kernel<<<(NN + 255) / 256, 256>>>();
    detect_kernel<<<8192 / 256, 256>>>(ei32);
    decode_hist_kernel<<<(NE + 255) / 256, 256>>>(ei32);
    scan_kernel<<<1, 1024>>>();
    fill_kernel<<<(NE + 255) / 256, 256>>>();

    dim3 ggrid((NN + 63) / 64, DD / 64);

    // x = relu(input @ W + b)   (A = input, C = g_x)
    gemm_kernel<<<ggrid, 256>>>(input, weight, bias, /*a_sel=*/0, /*c_sel=*/0, /*relu=*/1);

    const int agg_blocks = (NN * 32 + 255) / 256;   // warp per node
    for (int l = 0; l < 2; l++) {
        // h = x @ conv_w[l]   (A = g_x, C = g_h)
        gemm_kernel<<<ggrid, 256>>>(nullptr, conv_w + (size_t)l * DD * DD,
                                    nullptr, /*a_sel=*/1, /*c_sel=*/1, /*relu=*/0);
        // fused: self-loop + neighbor gather + bias + relu
        aggregate_kernel<<<agg_blocks, 256>>>(conv_b + l * DD,
                                              out, /*o_sel=*/(l == 0) ? 0 : 1);
    }
}

// round 5
// speedup vs baseline: 1.7252x; 1.5202x over previous
#include <cuda_runtime.h>

#define NN 50000
#define NE 800000
#define DD 256
#define SCAN_BLK 512
#define SCAN_NB  ((NN + SCAN_BLK - 1) / SCAN_BLK)   // 98

// Static scratch (no allocations allowed): ~113 MB.
__device__ float g_x[NN * DD];      // current activations
__device__ float g_h[NN * DD];      // post-GEMM, pre-aggregation
__device__ float g_dinv[NN];
__device__ int   g_src[NE];
__device__ int   g_dst[NE];
__device__ int   g_esrc[NE];        // CSR: src ids grouped by dst
__device__ int   g_cnt[NN];         // in-degree (edges only)
__device__ int   g_rowstart[NN + 1];
__device__ int   g_fill[NN];
__device__ int   g_bsum[SCAN_NB];
__device__ int   g_boff[SCAN_NB];
__device__ int   g_odd_nonzero;     // dtype sniffer flag

// ---------------------------------------------------------------------------
// Setup: dtype sniff, decode+histogram, 3-pass scan, CSR fill
// ---------------------------------------------------------------------------
__global__ void init_kernel() {
    int i = blockIdx.x * blockDim.x + threadIdx.x;
    if (i < NN) g_cnt[i] = 0;
    if (i == 0) g_odd_nonzero = 0;
}

// Sample first 8192 int32 words; int64 data => all odd words are zero.
__global__ void detect_kernel(const int* __restrict__ ei32) {
    int i = blockIdx.x * blockDim.x + threadIdx.x;   // 0..8191
    if ((i & 1) && ei32[i] != 0) atomicOr(&g_odd_nonzero, 1);
}

__global__ void decode_hist_kernel(const int* __restrict__ ei32) {
    int e = blockIdx.x * blockDim.x + threadIdx.x;
    if (e >= NE) return;
    int s, d;
    if (g_odd_nonzero) {            // genuinely int32: [src[NE] | dst[NE]]
        s = ei32[e];
        d = ei32[NE + e];
    } else {                        // int64: low words at even offsets
        s = ei32[2 * e];
        d = ei32[2 * (NE + e)];
    }
    g_src[e] = s;
    g_dst[e] = d;
    atomicAdd(&g_cnt[d], 1);
}

// Pass 1: per-block sums of g_cnt
__global__ void __launch_bounds__(SCAN_BLK) partial_sum_kernel() {
    __shared__ int s[SCAN_BLK];
    int t = threadIdx.x;
    int i = blockIdx.x * SCAN_BLK + t;
    s[t] = (i < NN) ? g_cnt[i] : 0;
    __syncthreads();
    for (int off = SCAN_BLK / 2; off > 0; off >>= 1) {
        if (t < off) s[t] += s[t + off];
        __syncthreads();
    }
    if (t == 0) g_bsum[blockIdx.x] = s[0];
}

// Pass 2: exclusive scan of 98 block sums (1 small block)
__global__ void __launch_bounds__(128) scan_partials_kernel() {
    __shared__ int s[128];
    int t = threadIdx.x;
    int v = (t < SCAN_NB) ? g_bsum[t] : 0;
    s[t] = v;
    __syncthreads();
    for (int off = 1; off < 128; off <<= 1) {
        int x = s[t];
        int add = (t >= off) ? s[t - off] : 0;
        __syncthreads();
        s[t] = x + add;
        __syncthreads();
    }
    if (t < SCAN_NB) g_boff[t] = s[t] - v;   // exclusive
}

// Pass 3: per-block local scan + offset; writes rowstart, dinv, fill
__global__ void __launch_bounds__(SCAN_BLK) write_rows_kernel() {
    __shared__ int s[SCAN_BLK];
    int t = threadIdx.x;
    int i = blockIdx.x * SCAN_BLK + t;
    int v = (i < NN) ? g_cnt[i] : 0;
    s[t] = v;
    __syncthreads();
    for (int off = 1; off < SCAN_BLK; off <<= 1) {
        int x = s[t];
        int add = (t >= off) ? s[t - off] : 0;
        __syncthreads();
        s[t] = x + add;
        __syncthreads();
    }
    if (i < NN) {
        g_rowstart[i] = g_boff[blockIdx.x] + s[t] - v;
        g_fill[i] = 0;
        g_dinv[i] = rsqrtf((float)v + 1.0f);   // +1 self loop
    }
    if (i == 0) g_rowstart[NN] = NE;
}

__global__ void fill_kernel() {
    int e = blockIdx.x * blockDim.x + threadIdx.x;
    if (e >= NE) return;
    int d = g_dst[e];
    int pos = g_rowstart[d] + atomicAdd(&g_fill[d], 1);
    g_esrc[pos] = g_src[e];
}

// ---------------------------------------------------------------------------
// SGEMM: C[M,256] = A[M,256] @ B[256,256] (+bias, +relu optional)
// 128x128 tile, 256 threads, 8x8 microtile, BK=8.
// a_sel: 0 -> A = Ain (external), 1 -> A = g_x ; C = g_x (c_sel=0) / g_h (1)
// ---------------------------------------------------------------------------
__global__ void __launch_bounds__(256)
gemm_kernel(const float* __restrict__ Ain, const float* __restrict__ B,
            const float* __restrict__ bias, int a_sel, int c_sel, int relu)
{
    const float* A = (a_sel == 0) ? Ain : g_x;
    float*       C = (c_sel == 0) ? g_x : g_h;

    __shared__ float As[8][128];
    __shared__ float Bs[8][128];

    const int tid  = threadIdx.x;
    const int row0 = blockIdx.x * 128;
    const int col0 = blockIdx.y * 128;
    const int ty = tid >> 4;          // 0..15 -> rows ty*8..+7
    const int tx = tid & 15;          // 0..15 -> cols tx*8..+7

    const int ar = tid >> 1;          // 0..127
    const int ak = (tid & 1) * 4;     // 0 or 4
    const int bk = tid >> 5;          // 0..7
    const int bc = (tid & 31) * 4;    // 0..124

    float acc[8][8] = {};

    for (int k0 = 0; k0 < DD; k0 += 8) {
        int r = row0 + ar;
        float4 av = (r < NN) ? *(const float4*)&A[(size_t)r * DD + k0 + ak]
                             : make_float4(0.f, 0.f, 0.f, 0.f);
        As[ak + 0][ar] = av.x;
        As[ak + 1][ar] = av.y;
        As[ak + 2][ar] = av.z;
        As[ak + 3][ar] = av.w;
        *(float4*)&Bs[bk][bc] = *(const float4*)&B[(size_t)(k0 + bk) * DD + col0 + bc];
        __syncthreads();
#pragma unroll
        for (int k = 0; k < 8; k++) {
            float a[8], b[8];
            *(float4*)&a[0] = *(const float4*)&As[k][ty * 8];
            *(float4*)&a[4] = *(const float4*)&As[k][ty * 8 + 4];
            *(float4*)&b[0] = *(const float4*)&Bs[k][tx * 8];
            *(float4*)&b[4] = *(const float4*)&Bs[k][tx * 8 + 4];
#pragma unroll
            for (int i = 0; i < 8; i++)
#pragma unroll
                for (int j = 0; j < 8; j++)
                    acc[i][j] += a[i] * b[j];
        }
        __syncthreads();
    }

    const int c = col0 + tx * 8;
#pragma unroll
    for (int i = 0; i < 8; i++) {
        int r = row0 + ty * 8 + i;
        if (r < NN) {
            float4 v0 = *(float4*)&acc[i][0];
            float4 v1 = *(float4*)&acc[i][4];
            if (bias) {
                float4 b0 = *(const float4*)&bias[c];
                float4 b1 = *(const float4*)&bias[c + 4];
                v0.x += b0.x; v0.y += b0.y; v0.z += b0.z; v0.w += b0.w;
                v1.x += b1.x; v1.y += b1.y; v1.z += b1.z; v1.w += b1.w;
            }
            if (relu) {
                v0.x = fmaxf(v0.x, 0.f); v0.y = fmaxf(v0.y, 0.f);
                v0.z = fmaxf(v0.z, 0.f); v0.w = fmaxf(v0.w, 0.f);
                v1.x = fmaxf(v1.x, 0.f); v1.y = fmaxf(v1.y, 0.f);
                v1.z = fmaxf(v1.z, 0.f); v1.w = fmaxf(v1.w, 0.f);
            }
            *(float4*)&C[(size_t)r * DD + c]     = v0;
            *(float4*)&C[(size_t)r * DD + c + 4] = v1;
        }
    }
}

// ---------------------------------------------------------------------------
// Fused CSR aggregation: one warp per dst node, 4-edge unroll.
//   o[d] = relu( bias + dinv[d]^2 * h[d] + sum_{s in N(d)} dinv[s]dinv[d] h[s] )
// ---------------------------------------------------------------------------
__global__ void __launch_bounds__(256)
aggregate_kernel(const float* __restrict__ bias, float* __restrict__ Oin, int o_sel)
{
    float* o = (o_sel == 0) ? g_x : Oin;
    int warp = (blockIdx.x * blockDim.x + threadIdx.x) >> 5;
    int lane = threadIdx.x & 31;
    if (warp >= NN) return;
    const int d = warp;
    const float dv = g_dinv[d];

    // self-loop init
    const float4* hd = (const float4*)(g_h + (size_t)d * DD);
    float4 a0 = hd[lane];
    float4 a1 = hd[lane + 32];
    const float s2 = dv * dv;
    a0.x *= s2; a0.y *= s2; a0.z *= s2; a0.w *= s2;
    a1.x *= s2; a1.y *= s2; a1.z *= s2; a1.w *= s2;

    const int start = g_rowstart[d];
    const int end   = g_rowstart[d + 1];
    int i = start;
    for (; i + 4 <= end; i += 4) {
        int   s0 = g_esrc[i],     s1 = g_esrc[i + 1];
        int   s2i = g_esrc[i + 2], s3 = g_esrc[i + 3];
        float n0 = dv * g_dinv[s0], n1 = dv * g_dinv[s1];
        float n2 = dv * g_dinv[s2i], n3 = dv * g_dinv[s3];
        const float4* h0 = (const float4*)(g_h + (size_t)s0 * DD);
        const float4* h1 = (const float4*)(g_h + (size_t)s1 * DD);
        const float4* h2 = (const float4*)(g_h + (size_t)s2i * DD);
        const float4* h3 = (const float4*)(g_h + (size_t)s3 * DD);
        float4 v00 = h0[lane], v01 = h0[lane + 32];
        float4 v10 = h1[lane], v11 = h1[lane + 32];
        float4 v20 = h2[lane], v21 = h2[lane + 32];
        float4 v30 = h3[lane], v31 = h3[lane + 32];
        a0.x += n0 * v00.x; a0.y += n0 * v00.y; a0.z += n0 * v00.z; a0.w += n0 * v00.w;
        a1.x += n0 * v01.x; a1.y += n0 * v01.y; a1.z += n0 * v01.z; a1.w += n0 * v01.w;
        a0.x += n1 * v10.x; a0.y += n1 * v10.y; a0.z += n1 * v10.z; a0.w += n1 * v10.w;
        a1.x += n1 * v11.x; a1.y += n1 * v11.y; a1.z += n1 * v11.z; a1.w += n1 * v11.w;
        a0.x += n2 * v20.x; a0.y += n2 * v20.y; a0.z += n2 * v20.z; a0.w += n2 * v20.w;
        a1.x += n2 * v21.x; a1.y += n2 * v21.y; a1.z += n2 * v21.z; a1.w += n2 * v21.w;
        a0.x += n3 * v30.x; a0.y += n3 * v30.y; a0.z += n3 * v30.z; a0.w += n3 * v30.w;
        a1.x += n3 * v31.x; a1.y += n3 * v31.y; a1.z += n3 * v31.z; a1.w += n3 * v31.w;
    }
    for (; i < end; i++) {
        int s0 = g_esrc[i];
        float n0 = dv * g_dinv[s0];
        const float4* h0 = (const float4*)(g_h + (size_t)s0 * DD);
        float4 v00 = h0[lane], v01 = h0[lane + 32];
        a0.x += n0 * v00.x; a0.y += n0 * v00.y; a0.z += n0 * v00.z; a0.w += n0 * v00.w;
        a1.x += n0 * v01.x; a1.y += n0 * v01.y; a1.z += n0 * v01.z; a1.w += n0 * v01.w;
    }

    // bias + relu + store
    float4 b0 = ((const float4*)bias)[lane];
    float4 b1 = ((const float4*)bias)[lane + 32];
    a0.x = fmaxf(a0.x + b0.x, 0.f); a0.y = fmaxf(a0.y + b0.y, 0.f);
    a0.z = fmaxf(a0.z + b0.z, 0.f); a0.w = fmaxf(a0.w + b0.w, 0.f);
    a1.x = fmaxf(a1.x + b1.x, 0.f); a1.y = fmaxf(a1.y + b1.y, 0.f);
    a1.z = fmaxf(a1.z + b1.z, 0.f); a1.w = fmaxf(a1.w + b1.w, 0.f);
    float4* orow = (float4*)(o + (size_t)d * DD);
    orow[lane] = a0;
    orow[lane + 32] = a1;
}

// ---------------------------------------------------------------------------
// Launch — kernels only; no runtime API calls (graph-capture safe).
// ---------------------------------------------------------------------------
extern "C" void kernel_launch(void* const* d_in, const int* in_sizes, int n_in,
                              void* d_out, int out_size)
{
    const float* input  = (const float*)d_in[0];
    const int*   ei32   = (const int*)d_in[1];     // int32 view; dtype sniffed on device
    const float* weight = (const float*)d_in[2];
    const float* bias   = (const float*)d_in[3];
    const float* conv_w = (const float*)d_in[4];
    const float* conv_b = (const float*)d_in[5];
    float*       out    = (float*)d_out;

    // CSR build
    init_kernel<<<(NN + 255) / 256, 256>>>();
    detect_kernel<<<8192 / 256, 256>>>(ei32);
    decode_hist_kernel<<<(NE + 255) / 256, 256>>>(ei32);
    partial_sum_kernel<<<SCAN_NB, SCAN_BLK>>>();
    scan_partials_kernel<<<1, 128>>>();
    write_rows_kernel<<<SCAN_NB, SCAN_BLK>>>();
    fill_kernel<<<(NE + 255) / 256, 256>>>();

    dim3 ggrid((NN + 127) / 128, DD / 128);

    // x = relu(input @ W + b)   (A = input, C = g_x)
    gemm_kernel<<<ggrid, 256>>>(input, weight, bias, /*a_sel=*/0, /*c_sel=*/0, /*relu=*/1);

    const int agg_blocks = (NN * 32 + 255) / 256;   // warp per node
    for (int l = 0; l < 2; l++) {
        // h = x @ conv_w[l]   (A = g_x, C = g_h)
        gemm_kernel<<<ggrid, 256>>>(nullptr, conv_w + (size_t)l * DD * DD,
                                    nullptr, /*a_sel=*/1, /*c_sel=*/1, /*relu=*/0);
        // fused: self-loop + neighbor gather + bias + relu
        aggregate_kernel<<<agg_blocks, 256>>>(conv_b + l * DD,
                                              out, /*o_sel=*/(l == 0) ? 0 : 1);
    }
}

// round 6
// speedup vs baseline: 3.2057x; 1.8582x over previous
#include <cuda_runtime.h>
#include <cstdint>

#define NN 50000
#define NE 800000
#define DD 256
#define SCAN_BLK 512
#define SCAN_NB  ((NN + SCAN_BLK - 1) / SCAN_BLK)   // 98
#define AST 140   // smem row stride (floats): conflict-free mma fragment loads

// Static scratch (no allocations allowed): ~113 MB.
__device__ float g_x[NN * DD];      // current activations
__device__ float g_h[NN * DD];      // post-GEMM, pre-aggregation
__device__ float g_dinv[NN];
__device__ int   g_src[NE];
__device__ int   g_dst[NE];
__device__ int   g_esrc[NE];        // CSR: src ids grouped by dst
__device__ int   g_cnt[NN];         // in-degree (edges only)
__device__ int   g_rowstart[NN + 1];
__device__ int   g_fill[NN];
__device__ int   g_bsum[SCAN_NB];
__device__ int   g_boff[SCAN_NB];
__device__ int   g_odd_nonzero;     // dtype sniffer flag

// ---------------------------------------------------------------------------
// Setup: dtype sniff, decode+histogram, 3-pass scan, CSR fill
// ---------------------------------------------------------------------------
__global__ void init_kernel() {
    int i = blockIdx.x * blockDim.x + threadIdx.x;
    if (i < NN) g_cnt[i] = 0;
    if (i == 0) g_odd_nonzero = 0;
}

// Sample first 8192 int32 words; int64 data => all odd words are zero.
__global__ void detect_kernel(const int* __restrict__ ei32) {
    int i = blockIdx.x * blockDim.x + threadIdx.x;   // 0..8191
    if ((i & 1) && ei32[i] != 0) atomicOr(&g_odd_nonzero, 1);
}

__global__ void decode_hist_kernel(const int* __restrict__ ei32) {
    int e = blockIdx.x * blockDim.x + threadIdx.x;
    if (e >= NE) return;
    int s, d;
    if (g_odd_nonzero) {            // genuinely int32: [src[NE] | dst[NE]]
        s = ei32[e];
        d = ei32[NE + e];
    } else {                        // int64: low words at even offsets
        s = ei32[2 * e];
        d = ei32[2 * (NE + e)];
    }
    g_src[e] = s;
    g_dst[e] = d;
    atomicAdd(&g_cnt[d], 1);
}

// Pass 1: per-block sums of g_cnt
__global__ void __launch_bounds__(SCAN_BLK) partial_sum_kernel() {
    __shared__ int s[SCAN_BLK];
    int t = threadIdx.x;
    int i = blockIdx.x * SCAN_BLK + t;
    s[t] = (i < NN) ? g_cnt[i] : 0;
    __syncthreads();
    for (int off = SCAN_BLK / 2; off > 0; off >>= 1) {
        if (t < off) s[t] += s[t + off];
        __syncthreads();
    }
    if (t == 0) g_bsum[blockIdx.x] = s[0];
}

// Pass 2: exclusive scan of 98 block sums (1 small block)
__global__ void __launch_bounds__(128) scan_partials_kernel() {
    __shared__ int s[128];
    int t = threadIdx.x;
    int v = (t < SCAN_NB) ? g_bsum[t] : 0;
    s[t] = v;
    __syncthreads();
    for (int off = 1; off < 128; off <<= 1) {
        int x = s[t];
        int add = (t >= off) ? s[t - off] : 0;
        __syncthreads();
        s[t] = x + add;
        __syncthreads();
    }
    if (t < SCAN_NB) g_boff[t] = s[t] - v;   // exclusive
}

// Pass 3: per-block local scan + offset; writes rowstart, dinv, fill
__global__ void __launch_bounds__(SCAN_BLK) write_rows_kernel() {
    __shared__ int s[SCAN_BLK];
    int t = threadIdx.x;
    int i = blockIdx.x * SCAN_BLK + t;
    int v = (i < NN) ? g_cnt[i] : 0;
    s[t] = v;
    __syncthreads();
    for (int off = 1; off < SCAN_BLK; off <<= 1) {
        int x = s[t];
        int add = (t >= off) ? s[t - off] : 0;
        __syncthreads();
        s[t] = x + add;
        __syncthreads();
    }
    if (i < NN) {
        g_rowstart[i] = g_boff[blockIdx.x] + s[t] - v;
        g_fill[i] = 0;
        g_dinv[i] = rsqrtf((float)v + 1.0f);   // +1 self loop
    }
    if (i == 0) g_rowstart[NN] = NE;
}

__global__ void fill_kernel() {
    int e = blockIdx.x * blockDim.x + threadIdx.x;
    if (e >= NE) return;
    int d = g_dst[e];
    int pos = g_rowstart[d] + atomicAdd(&g_fill[d], 1);
    g_esrc[pos] = g_src[e];
}

// ---------------------------------------------------------------------------
// TF32 tensor-core GEMM: C[M,256] = A[M,256] @ B[256,256] (+bias, +relu)
// 128x128 tile, 256 threads (8 warps, 2M x 4N), warp tile 64x32,
// mma.sync.m16n8k8.tf32, BK=16, register-prefetch software pipeline.
// a_sel: 0 -> A = Ain (external), 1 -> A = g_x ; C = g_x (c_sel=0) / g_h (1)
// ---------------------------------------------------------------------------
__device__ __forceinline__ uint32_t f2tf32(float f) {
    uint32_t u;
    asm("cvt.rna.tf32.f32 %0, %1;" : "=r"(u) : "f"(f));
    return u;
}

__global__ void __launch_bounds__(256)
gemm_kernel(const float* __restrict__ Ain, const float* __restrict__ B,
            const float* __restrict__ bias, int a_sel, int c_sel, int relu)
{
    const float* A = (a_sel == 0) ? Ain : g_x;
    float*       C = (c_sel == 0) ? g_x : g_h;

    __shared__ uint32_t As[16 * AST];   // [k][m], tf32 bits
    __shared__ uint32_t Bs[16 * AST];   // [k][n], tf32 bits

    const int tid  = threadIdx.x;
    const int lane = tid & 31;
    const int w    = tid >> 5;
    const int mw   = (w & 1) << 6;      // warp M offset: 0 / 64
    const int nw   = (w >> 1) << 5;     // warp N offset: 0/32/64/96
    const int gid  = lane >> 2;         // 0..7
    const int tg   = lane & 3;          // 0..3
    const int row0 = blockIdx.x * 128;
    const int col0 = blockIdx.y * 128;

    float acc[4][4][4];
#pragma unroll
    for (int mt = 0; mt < 4; mt++)
#pragma unroll
        for (int nt = 0; nt < 4; nt++)
#pragma unroll
            for (int q = 0; q < 4; q++) acc[mt][nt][q] = 0.0f;

    float4 av[2], bv[2];

    // prefetch chunk 0
#pragma unroll
    for (int i = 0; i < 2; i++) {
        int idx = tid + i * 256;
        int r = row0 + (idx >> 2);
        int kq = idx & 3;
        av[i] = (r < NN) ? *(const float4*)&A[(size_t)r * DD + kq * 4]
                         : make_float4(0.f, 0.f, 0.f, 0.f);
        int kr = idx >> 5, nq = idx & 31;
        bv[i] = *(const float4*)&B[(size_t)kr * DD + col0 + nq * 4];
    }

    for (int c = 0; c < 16; c++) {
        __syncthreads();
        // store prefetched chunk to smem (cvt to tf32)
#pragma unroll
        for (int i = 0; i < 2; i++) {
            int idx = tid + i * 256;
            int r = idx >> 2, kq = idx & 3;
            As[(kq * 4 + 0) * AST + r] = f2tf32(av[i].x);
            As[(kq * 4 + 1) * AST + r] = f2tf32(av[i].y);
            As[(kq * 4 + 2) * AST + r] = f2tf32(av[i].z);
            As[(kq * 4 + 3) * AST + r] = f2tf32(av[i].w);
            int kr = idx >> 5, nq = idx & 31;
            uint4 bu;
            bu.x = f2tf32(bv[i].x); bu.y = f2tf32(bv[i].y);
            bu.z = f2tf32(bv[i].z); bu.w = f2tf32(bv[i].w);
            *(uint4*)&Bs[kr * AST + nq * 4] = bu;
        }
        __syncthreads();
        // prefetch next chunk (latency hidden behind MMAs below)
        if (c < 15) {
            int k0 = (c + 1) * 16;
#pragma unroll
            for (int i = 0; i < 2; i++) {
                int idx = tid + i * 256;
                int r = row0 + (idx >> 2);
                int kq = idx & 3;
                av[i] = (r < NN) ? *(const float4*)&A[(size_t)r * DD + k0 + kq * 4]
                                 : make_float4(0.f, 0.f, 0.f, 0.f);
                int kr = idx >> 5, nq = idx & 31;
                bv[i] = *(const float4*)&B[(size_t)(k0 + kr) * DD + col0 + nq * 4];
            }
        }
        // compute: 2 k8-substeps, 4x4 mma each
#pragma unroll
        for (int sub = 0; sub < 16; sub += 8) {
            uint32_t bf[4][2];
#pragma unroll
            for (int nt = 0; nt < 4; nt++) {
                bf[nt][0] = Bs[(sub + tg) * AST + nw + nt * 8 + gid];
                bf[nt][1] = Bs[(sub + tg + 4) * AST + nw + nt * 8 + gid];
            }
#pragma unroll
            for (int mt = 0; mt < 4; mt++) {
                uint32_t a0 = As[(sub + tg) * AST + mw + mt * 16 + gid];
                uint32_t a1 = As[(sub + tg) * AST + mw + mt * 16 + gid + 8];
                uint32_t a2 = As[(sub + tg + 4) * AST + mw + mt * 16 + gid];
                uint32_t a3 = As[(sub + tg + 4) * AST + mw + mt * 16 + gid + 8];
#pragma unroll
                for (int nt = 0; nt < 4; nt++) {
                    asm("mma.sync.aligned.m16n8k8.row.col.f32.tf32.tf32.f32 "
                        "{%0,%1,%2,%3}, {%4,%5,%6,%7}, {%8,%9}, {%0,%1,%2,%3};"
                        : "+f"(acc[mt][nt][0]), "+f"(acc[mt][nt][1]),
                          "+f"(acc[mt][nt][2]), "+f"(acc[mt][nt][3])
                        : "r"(a0), "r"(a1), "r"(a2), "r"(a3),
                          "r"(bf[nt][0]), "r"(bf[nt][1]));
                }
            }
        }
    }

    // epilogue: c0,c1 -> (row gid, cols 2tg,2tg+1); c2,c3 -> row gid+8
    float2 bb[4];
    if (bias) {
#pragma unroll
        for (int nt = 0; nt < 4; nt++) {
            int cc = col0 + nw + nt * 8 + 2 * tg;
            bb[nt].x = bias[cc];
            bb[nt].y = bias[cc + 1];
        }
    }
#pragma unroll
    for (int mt = 0; mt < 4; mt++) {
        int r = row0 + mw + mt * 16 + gid;
#pragma unroll
        for (int nt = 0; nt < 4; nt++) {
            int cc = col0 + nw + nt * 8 + 2 * tg;
            float2 v0 = make_float2(acc[mt][nt][0], acc[mt][nt][1]);
            float2 v1 = make_float2(acc[mt][nt][2], acc[mt][nt][3]);
            if (bias) {
                v0.x += bb[nt].x; v0.y += bb[nt].y;
                v1.x += bb[nt].x; v1.y += bb[nt].y;
            }
            if (relu) {
                v0.x = fmaxf(v0.x, 0.f); v0.y = fmaxf(v0.y, 0.f);
                v1.x = fmaxf(v1.x, 0.f); v1.y = fmaxf(v1.y, 0.f);
            }
            if (r < NN)     *(float2*)&C[(size_t)r * DD + cc]       = v0;
            if (r + 8 < NN) *(float2*)&C[(size_t)(r + 8) * DD + cc] = v1;
        }
    }
}

// ---------------------------------------------------------------------------
// Fused CSR aggregation: one warp per dst node, 4-edge unroll.
//   o[d] = relu( bias + dinv[d]^2 * h[d] + sum_{s in N(d)} dinv[s]dinv[d] h[s] )
// ---------------------------------------------------------------------------
__global__ void __launch_bounds__(256)
aggregate_kernel(const float* __restrict__ bias, float* __restrict__ Oin, int o_sel)
{
    float* o = (o_sel == 0) ? g_x : Oin;
    int warp = (blockIdx.x * blockDim.x + threadIdx.x) >> 5;
    int lane = threadIdx.x & 31;
    if (warp >= NN) return;
    const int d = warp;
    const float dv = g_dinv[d];

    // self-loop init
    const float4* hd = (const float4*)(g_h + (size_t)d * DD);
    float4 a0 = hd[lane];
    float4 a1 = hd[lane + 32];
    const float s2 = dv * dv;
    a0.x *= s2; a0.y *= s2; a0.z *= s2; a0.w *= s2;
    a1.x *= s2; a1.y *= s2; a1.z *= s2; a1.w *= s2;

    const int start = g_rowstart[d];
    const int end   = g_rowstart[d + 1];
    int i = start;
    for (; i + 4 <= end; i += 4) {
        int   s0 = g_esrc[i],      s1 = g_esrc[i + 1];
        int   s2i = g_esrc[i + 2], s3 = g_esrc[i + 3];
        float n0 = dv * g_dinv[s0],  n1 = dv * g_dinv[s1];
        float n2 = dv * g_dinv[s2i], n3 = dv * g_dinv[s3];
        const float4* h0 = (const float4*)(g_h + (size_t)s0 * DD);
        const float4* h1 = (const float4*)(g_h + (size_t)s1 * DD);
        const float4* h2 = (const float4*)(g_h + (size_t)s2i * DD);
        const float4* h3 = (const float4*)(g_h + (size_t)s3 * DD);
        float4 v00 = h0[lane], v01 = h0[lane + 32];
        float4 v10 = h1[lane], v11 = h1[lane + 32];
        float4 v20 = h2[lane], v21 = h2[lane + 32];
        float4 v30 = h3[lane], v31 = h3[lane + 32];
        a0.x += n0 * v00.x; a0.y += n0 * v00.y; a0.z += n0 * v00.z; a0.w += n0 * v00.w;
        a1.x += n0 * v01.x; a1.y += n0 * v01.y; a1.z += n0 * v01.z; a1.w += n0 * v01.w;
        a0.x += n1 * v10.x; a0.y += n1 * v10.y; a0.z += n1 * v10.z; a0.w += n1 * v10.w;
        a1.x += n1 * v11.x; a1.y += n1 * v11.y; a1.z += n1 * v11.z; a1.w += n1 * v11.w;
        a0.x += n2 * v20.x; a0.y += n2 * v20.y; a0.z += n2 * v20.z; a0.w += n2 * v20.w;
        a1.x += n2 * v21.x; a1.y += n2 * v21.y; a1.z += n2 * v21.z; a1.w += n2 * v21.w;
        a0.x += n3 * v30.x; a0.y += n3 * v30.y; a0.z += n3 * v30.z; a0.w += n3 * v30.w;
        a1.x += n3 * v31.x; a1.y += n3 * v31.y; a1.z += n3 * v31.z; a1.w += n3 * v31.w;
    }
    for (; i < end; i++) {
        int s0 = g_esrc[i];
        float n0 = dv * g_dinv[s0];
        const float4* h0 = (const float4*)(g_h + (size_t)s0 * DD);
        float4 v00 = h0[lane], v01 = h0[lane + 32];
        a0.x += n0 * v00.x; a0.y += n0 * v00.y; a0.z += n0 * v00.z; a0.w += n0 * v00.w;
        a1.x += n0 * v01.x; a1.y += n0 * v01.y; a1.z += n0 * v01.z; a1.w += n0 * v01.w;
    }

    // bias + relu + store
    float4 b0 = ((const float4*)bias)[lane];
    float4 b1 = ((const float4*)bias)[lane + 32];
    a0.x = fmaxf(a0.x + b0.x, 0.f); a0.y = fmaxf(a0.y + b0.y, 0.f);
    a0.z = fmaxf(a0.z + b0.z, 0.f); a0.w = fmaxf(a0.w + b0.w, 0.f);
    a1.x = fmaxf(a1.x + b1.x, 0.f); a1.y = fmaxf(a1.y + b1.y, 0.f);
    a1.z = fmaxf(a1.z + b1.z, 0.f); a1.w = fmaxf(a1.w + b1.w, 0.f);
    float4* orow = (float4*)(o + (size_t)d * DD);
    orow[lane] = a0;
    orow[lane + 32] = a1;
}

// ---------------------------------------------------------------------------
// Launch — kernels only; no runtime API calls (graph-capture safe).
// ---------------------------------------------------------------------------
extern "C" void kernel_launch(void* const* d_in, const int* in_sizes, int n_in,
                              void* d_out, int out_size)
{
    const float* input  = (const float*)d_in[0];
    const int*   ei32   = (const int*)d_in[1];     // int32 view; dtype sniffed on device
    const float* weight = (const float*)d_in[2];
    const float* bias   = (const float*)d_in[3];
    const float* conv_w = (const float*)d_in[4];
    const float* conv_b = (const float*)d_in[5];
    float*       out    = (float*)d_out;

    // CSR build
    init_kernel<<<(NN + 255) / 256, 256>>>();
    detect_kernel<<<8192 / 256, 256>>>(ei32);
    decode_hist_kernel<<<(NE + 255) / 256, 256>>>(ei32);
    partial_sum_kernel<<<SCAN_NB, SCAN_BLK>>>();
    scan_partials_kernel<<<1, 128>>>();
    write_rows_kernel<<<SCAN_NB, SCAN_BLK>>>();
    fill_kernel<<<(NE + 255) / 256, 256>>>();

    dim3 ggrid((NN + 127) / 128, DD / 128);

    // x = relu(input @ W + b)   (A = input, C = g_x)
    gemm_kernel<<<ggrid, 256>>>(input, weight, bias, /*a_sel=*/0, /*c_sel=*/0, /*relu=*/1);

    const int agg_blocks = (NN * 32 + 255) / 256;   // warp per node
    for (int l = 0; l < 2; l++) {
        // h = x @ conv_w[l]   (A = g_x, C = g_h)
        gemm_kernel<<<ggrid, 256>>>(nullptr, conv_w + (size_t)l * DD * DD,
                                    nullptr, /*a_sel=*/1, /*c_sel=*/1, /*relu=*/0);
        // fused: self-loop + neighbor gather + bias + relu
        aggregate_kernel<<<agg_blocks, 256>>>(conv_b + l * DD,
                                              out, /*o_sel=*/(l == 0) ? 0 : 1);
    }
}